// round 2
// baseline (speedup 1.0000x reference)
#include <cuda_runtime.h>
#include <math.h>

#define MD 4096
#define DD 64
#define NJB 32
#define FFC 0.999f
#define REGC 0.01f
#define JIT 1e-10f
#define INV2LS2 (1.0f/128.0f)

#define OFF_MU   ((size_t)0)
#define OFF_SIG  ((size_t)16384)
#define OFF_Q    (OFF_SIG + (size_t)MD*MD)
#define OFF_DICT (OFF_Q   + (size_t)MD*MD)
#define OFF_TI   (OFF_DICT + (size_t)MD*DD)
#define OFF_NN   (OFF_TI + MD)
#define OFF_ND   (OFF_NN + 4)

// -------- scratch (device globals; allocations forbidden) --------
static __device__ float g_kdx[MD], g_alloc[MD], g_norm[MD];
static __device__ float g_q[MD], g_h[MD], g_Qh[MD], g_Qmu[4*MD];
static __device__ float g_hpart[NJB*MD];
static __device__ float g_colp[MD];
static __device__ float g_pval[16];
static __device__ int   g_pidx[16];
static __device__ float gs_pu, gs_pm[4], gs_qh, gs_npv, gs_pv, gs_c[4];
static __device__ float gs_critM, gs_denom, gs_qp, gs_tval;
static __device__ int   gs_prune;

// -------- K_dx, alloc, row norms --------
__global__ void k_kdx(const float* __restrict__ dict, const float* __restrict__ x,
                      const float* __restrict__ ti) {
    __shared__ float xs[DD];
    int tid = threadIdx.x;
    if (tid < DD) xs[tid] = x[tid];
    __syncthreads();
    int i = blockIdx.x * 256 + tid;
    const float* dr = dict + (size_t)i * DD;
    float a2 = 0.f, ip = 0.f, x2 = 0.f;
#pragma unroll
    for (int k = 0; k < DD; k++) { float d = dr[k], xv = xs[k]; a2 += d*d; ip += d*xv; x2 += xv*xv; }
    float d2 = fmaxf(a2 + x2 - 2.0f*ip, 0.0f);
    float al = (ti[i] >= 0.0f) ? 1.0f : 0.0f;
    g_kdx[i] = __expf(-d2 * INV2LS2) * al;
    g_alloc[i] = al;
    g_norm[i] = a2;
}

// -------- q = Q@kdx, Qmu = sqrt(FF)*Q@mu (warp per row) --------
__global__ void k_matvec5(const float* __restrict__ Q, const float* __restrict__ mu) {
    int gw = (blockIdx.x * 256 + threadIdx.x) >> 5;
    int lane = threadIdx.x & 31;
    const float4* Qr = reinterpret_cast<const float4*>(Q) + (size_t)gw * (MD/4);
    const float4* K4 = reinterpret_cast<const float4*>(g_kdx);
    const float4* M4 = reinterpret_cast<const float4*>(mu);
    float s[5] = {0,0,0,0,0};
    for (int jb = lane; jb < MD/4; jb += 32) {
        float4 qv = Qr[jb], kv = K4[jb];
        s[0] += qv.x*kv.x + qv.y*kv.y + qv.z*kv.z + qv.w*kv.w;
#pragma unroll
        for (int yd = 0; yd < 4; yd++) {
            float4 mv = M4[yd*(MD/4) + jb];
            s[1+yd] += qv.x*mv.x + qv.y*mv.y + qv.z*mv.z + qv.w*mv.w;
        }
    }
#pragma unroll
    for (int o = 16; o > 0; o >>= 1)
#pragma unroll
        for (int r = 0; r < 5; r++) s[r] += __shfl_xor_sync(0xffffffffu, s[r], o);
    if (lane == 0) {
        g_q[gw] = s[0];
        float sf = sqrtf(FFC);
#pragma unroll
        for (int yd = 0; yd < 4; yd++) g_Qmu[yd*MD + gw] = sf * s[1+yd];
    }
}

// -------- scalars 1: pu, pred_mean --------
__global__ void k_scalars1(const float* __restrict__ mu) {
    __shared__ float red[5][8];
    int tid = threadIdx.x;
    float s[5] = {0,0,0,0,0};
    for (int i = tid; i < MD; i += 256) {
        float qi = g_q[i];
        s[0] += g_kdx[i] * qi;
#pragma unroll
        for (int yd = 0; yd < 4; yd++) s[1+yd] += qi * mu[yd*MD + i];
    }
#pragma unroll
    for (int o = 16; o > 0; o >>= 1)
#pragma unroll
        for (int r = 0; r < 5; r++) s[r] += __shfl_xor_sync(0xffffffffu, s[r], o);
    if ((tid & 31) == 0)
#pragma unroll
        for (int r = 0; r < 5; r++) red[r][tid >> 5] = s[r];
    __syncthreads();
    if (tid == 0) {
        float t[5];
#pragma unroll
        for (int r = 0; r < 5; r++) { t[r] = 0.f;
#pragma unroll
            for (int w = 0; w < 8; w++) t[r] += red[r][w]; }
        gs_pu = fmaxf((1.0f + JIT) - t[0], 0.0f);
        float sf = sqrtf(FFC);
#pragma unroll
        for (int yd = 0; yd < 4; yd++) gs_pm[yd] = sf * t[1+yd];
    }
}

// -------- sig = FF*sigma + (1-FF)*Kdd, fused partial h (128x128 tiles) -------
#define SMEM_SIG ((2*64*128 + 5*128) * 4)
__global__ void k_sig(const float* __restrict__ dict, const float* __restrict__ sigma,
                      float* __restrict__ out) {
    extern __shared__ float sm[];
    float* As = sm;                 // [64][128] k-major
    float* Bs = As + 64*128;
    float* qs = Bs + 64*128;
    float* nI = qs + 128; float* nJ = nI + 128;
    float* aI = nJ + 128; float* aJ = aI + 128;

    int tx = threadIdx.x, ty = threadIdx.y;
    int tid = ty * 16 + tx;
    int I0 = blockIdx.y * 128, J0 = blockIdx.x * 128;

    for (int idx = tid; idx < 2048; idx += 256) {
        int r = idx & 127, kq = idx >> 7;   // kq 0..15
        float4 v = *reinterpret_cast<const float4*>(dict + (size_t)(I0+r)*DD + kq*4);
        As[(kq*4+0)*128 + r] = v.x; As[(kq*4+1)*128 + r] = v.y;
        As[(kq*4+2)*128 + r] = v.z; As[(kq*4+3)*128 + r] = v.w;
        float4 w = *reinterpret_cast<const float4*>(dict + (size_t)(J0+r)*DD + kq*4);
        Bs[(kq*4+0)*128 + r] = w.x; Bs[(kq*4+1)*128 + r] = w.y;
        Bs[(kq*4+2)*128 + r] = w.z; Bs[(kq*4+3)*128 + r] = w.w;
    }
    if (tid < 128) {
        qs[tid] = g_q[J0 + tid];
        nJ[tid] = g_norm[J0 + tid]; aJ[tid] = g_alloc[J0 + tid];
        nI[tid] = g_norm[I0 + tid]; aI[tid] = g_alloc[I0 + tid];
    }
    __syncthreads();

    float acc[64];
#pragma unroll
    for (int u = 0; u < 64; u++) acc[u] = 0.f;

#pragma unroll 4
    for (int k = 0; k < 64; k++) {
        float4 a0 = *reinterpret_cast<const float4*>(As + k*128 + ty*8);
        float4 a1 = *reinterpret_cast<const float4*>(As + k*128 + ty*8 + 4);
        float4 b0 = *reinterpret_cast<const float4*>(Bs + k*128 + tx*8);
        float4 b1 = *reinterpret_cast<const float4*>(Bs + k*128 + tx*8 + 4);
        float a[8] = {a0.x,a0.y,a0.z,a0.w,a1.x,a1.y,a1.z,a1.w};
        float b[8] = {b0.x,b0.y,b0.z,b0.w,b1.x,b1.y,b1.z,b1.w};
#pragma unroll
        for (int u = 0; u < 8; u++)
#pragma unroll
            for (int v = 0; v < 8; v++) acc[u*8+v] += a[u]*b[v];
    }

#pragma unroll
    for (int u = 0; u < 8; u++) {
        int i = I0 + ty*8 + u;
        float ni = nI[ty*8+u], ai = aI[ty*8+u];
        const float* srow = sigma + (size_t)i*MD + J0;
        float* orow = out + OFF_SIG + (size_t)i*MD + J0;
        float hsum = 0.f;
#pragma unroll
        for (int vb = 0; vb < 2; vb++) {
            int j0 = tx*8 + vb*4;
            float4 sg = __ldcs(reinterpret_cast<const float4*>(srow + j0));
            float sv[4] = {sg.x, sg.y, sg.z, sg.w};
            float ov[4];
#pragma unroll
            for (int c = 0; c < 4; c++) {
                int j = j0 + c;
                float d2 = fmaxf(ni + nJ[j] - 2.0f*acc[u*8 + vb*4 + c], 0.0f);
                float kdd = __expf(-d2 * INV2LS2) * ai * aJ[j];
                float s = FFC * sv[c] + (1.0f - FFC) * kdd;
                hsum += s * qs[j];
                ov[c] = s;
            }
            float4 o; o.x=ov[0]; o.y=ov[1]; o.z=ov[2]; o.w=ov[3];
            __stcs(reinterpret_cast<float4*>(orow + j0), o);
        }
#pragma unroll
        for (int off = 8; off > 0; off >>= 1)
            hsum += __shfl_xor_sync(0xffffffffu, hsum, off, 16);
        if (tx == 0) g_hpart[(size_t)blockIdx.x*MD + i] = hsum;
    }
}

__global__ void k_hreduce() {
    int i = blockIdx.x * 256 + threadIdx.x;
    float s = 0.f;
#pragma unroll
    for (int b = 0; b < NJB; b++) s += g_hpart[(size_t)b*MD + i];
    g_h[i] = s;
}

// -------- scalars 2: qh, npv, pv, c; nnum/nden out; criterion[M] --------
__global__ void k_scalars2(const float* __restrict__ y, const float* __restrict__ nn,
                           const float* __restrict__ nd, float* __restrict__ out) {
    __shared__ float red[8];
    int tid = threadIdx.x;
    float s = 0.f;
    for (int i = tid; i < MD; i += 256) s += g_q[i] * g_h[i];
#pragma unroll
    for (int o = 16; o > 0; o >>= 1) s += __shfl_xor_sync(0xffffffffu, s, o);
    if ((tid & 31) == 0) red[tid >> 5] = s;
    __syncthreads();
    if (tid == 0) {
        float qh = 0.f;
#pragma unroll
        for (int w = 0; w < 8; w++) qh += red[w];
        gs_qh = qh;
        float pu = gs_pu;
        float npv = fmaxf(pu + qh, 0.0f);
        float pv = REGC + npv;
        gs_npv = npv; gs_pv = pv;
        float cm = 0.f;
#pragma unroll
        for (int yd = 0; yd < 4; yd++) {
            float dy = y[yd] - gs_pm[yd];
            float c = dy / pv;
            gs_c[yd] = c;
            out[OFF_NN + yd] = nn[yd] + FFC * dy * dy / pv;
            cm += fabsf(c * (npv - qh));
        }
        out[OFF_ND] = nd[0] + FFC;
        gs_critM = cm;
    }
}

// -------- Qh = Q@h --------
__global__ void k_Qh(const float* __restrict__ Q) {
    int gw = (blockIdx.x * 256 + threadIdx.x) >> 5;
    int lane = threadIdx.x & 31;
    const float4* Qr = reinterpret_cast<const float4*>(Q) + (size_t)gw * (MD/4);
    const float4* H4 = reinterpret_cast<const float4*>(g_h);
    float s = 0.f;
    for (int jb = lane; jb < MD/4; jb += 32) {
        float4 qv = Qr[jb], hv = H4[jb];
        s += qv.x*hv.x + qv.y*hv.y + qv.z*hv.z + qv.w*hv.w;
    }
#pragma unroll
    for (int o = 16; o > 0; o >>= 1) s += __shfl_xor_sync(0xffffffffu, s, o);
    if (lane == 0) g_Qh[gw] = s;
}

// -------- criterion per index + per-block argmin --------
__global__ void k_crit(const float* __restrict__ Q) {
    __shared__ float sv[256]; __shared__ int si[256];
    int tid = threadIdx.x;
    int i = blockIdx.x * 256 + tid;
    float pu = gs_pu;
    float cv;
    if (pu < JIT) {
        cv = 1.0f;
    } else {
        float qi = g_q[i];
        float dq = (g_alloc[i] != 0.f) ? (Q[(size_t)i*MD + i] + qi*qi/pu)
                                       : __int_as_float(0x7f800000);
        float r = qi / pu;
        float qhm = gs_qh - gs_npv;
        float qhv = g_Qh[i];
        float s = 0.f;
#pragma unroll
        for (int yd = 0; yd < 4; yd++) {
            float num = g_Qmu[yd*MD + i] + gs_c[yd]*qhv + r*gs_c[yd]*qhm;
            s += fabsf(num / dq);
        }
        cv = s;
    }
    sv[tid] = cv; si[tid] = i;
    __syncthreads();
    for (int st = 128; st > 0; st >>= 1) {
        if (tid < st) {
            float a = sv[tid], b = sv[tid+st];
            if (b < a || (b == a && si[tid+st] < si[tid])) { sv[tid] = b; si[tid] = si[tid+st]; }
        }
        __syncthreads();
    }
    if (tid == 0) { g_pval[blockIdx.x] = sv[0]; g_pidx[blockIdx.x] = si[0]; }
}

// -------- argmin finalize + prune scalars --------
__global__ void k_finalize(const float* __restrict__ Q, const int* __restrict__ tptr) {
    if (threadIdx.x != 0) return;
    float pu = gs_pu;
    int bi;
    if (pu < JIT) {
        bi = MD;
    } else {
        float bv = g_pval[0]; bi = g_pidx[0];
        for (int b = 1; b < 16; b++) {
            float v = g_pval[b]; int ix = g_pidx[b];
            if (v < bv || (v == bv && ix < bi)) { bv = v; bi = ix; }
        }
        if (gs_critM < bv) bi = MD;   // index M is last; ties keep earlier
    }
    gs_prune = bi;
    float qp = (bi < MD) ? g_q[bi] : 0.0f;
    gs_qp = qp;
    bool xal = (bi == MD) ? true : (g_alloc[bi] != 0.f);
    float qaa = (bi == MD) ? (1.0f/pu) : (Q[(size_t)bi*MD + bi] + qp*qp/pu);
    gs_denom = xal ? qaa : __int_as_float(0x7f800000);
    int bits = tptr[0];
    gs_tval = (bits >= 0 && bits < (1 << 26)) ? (float)bits : __int_as_float(bits);
}

__global__ void k_colp(const float* __restrict__ Q) {
    int i = blockIdx.x * 256 + threadIdx.x;
    int p = gs_prune;
    g_colp[i] = (p < MD) ? Q[(size_t)i*MD + p] : 0.0f;
}

// -------- Q_n (row per block) --------
__device__ __forceinline__ float qn_elem(int p, bool rowp, int j, float Qij,
                                         float qi, float qj, float colj,
                                         float qp, float ipu, float Bi, float dinv) {
    float m, Bj;
    if (p < MD) {
        if (rowp) m = (j == p) ? ipu : (-qj * ipu);
        else      m = (j == p) ? (-qi * ipu) : (Qij + qi*qj*ipu);
        Bj = (j == p) ? (-qp * ipu) : (colj + qj*qp*ipu);
    } else {
        m  = Qij + qi*qj*ipu;
        Bj = -qj * ipu;
    }
    return m - Bi * Bj * dinv;
}

__global__ void k_Qn(const float* __restrict__ Q, float* __restrict__ out) {
    int i = blockIdx.x;
    int tid = threadIdx.x;
    int p = gs_prune;
    float pu = gs_pu, qp = gs_qp, qi = g_q[i];
    float ipu = 1.0f / pu;
    float dinv = 1.0f / gs_denom;
    bool rowp = (p < MD) && (i == p);
    float Bi = (p < MD) ? (rowp ? (-qp*ipu) : (g_colp[i] + qi*qp*ipu)) : (-qi*ipu);
    const float4* Qr = reinterpret_cast<const float4*>(Q + (size_t)i*MD);
    float4* orow = reinterpret_cast<float4*>(out + OFF_Q + (size_t)i*MD);
    const float4* q4 = reinterpret_cast<const float4*>(g_q);
    const float4* c4 = reinterpret_cast<const float4*>(g_colp);
    for (int jb = tid; jb < MD/4; jb += 256) {
        float4 qv = __ldcs(&Qr[jb]); float4 qq = q4[jb]; float4 cc = c4[jb];
        int j0 = jb * 4;
        float4 o;
        o.x = qn_elem(p, rowp, j0+0, qv.x, qi, qq.x, cc.x, qp, ipu, Bi, dinv);
        o.y = qn_elem(p, rowp, j0+1, qv.y, qi, qq.y, cc.y, qp, ipu, Bi, dinv);
        o.z = qn_elem(p, rowp, j0+2, qv.z, qi, qq.z, cc.z, qp, ipu, Bi, dinv);
        o.w = qn_elem(p, rowp, j0+3, qv.w, qi, qq.w, cc.w, qp, ipu, Bi, dinv);
        __stcs(&orow[jb], o);
    }
}

// -------- sig_n (row per block, in place on out) --------
__global__ void k_sign(const float* __restrict__ TI, float* __restrict__ out) {
    int i = blockIdx.x;
    int tid = threadIdx.x;
    int p = gs_prune;
    float npv = gs_npv, ivp = 1.0f / gs_pv, tval = gs_tval;
    bool rowp = (p < MD) && (i == p);
    float hi = g_h[i];
    float tni = rowp ? tval : TI[i];
    float mi = (tni >= 0.f) ? 1.f : 0.f;
    float ppi = rowp ? npv : hi;
    float4* row = reinterpret_cast<float4*>(out + OFF_SIG + (size_t)i*MD);
    const float4* h4 = reinterpret_cast<const float4*>(g_h);
    const float4* t4 = reinterpret_cast<const float4*>(TI);
    for (int jb = tid; jb < MD/4; jb += 256) {
        float4 sg = __ldcs(&row[jb]);
        float4 hh = h4[jb];
        float4 tt = t4[jb];
        float sv[4] = {sg.x,sg.y,sg.z,sg.w};
        float hv[4] = {hh.x,hh.y,hh.z,hh.w};
        float tv[4] = {tt.x,tt.y,tt.z,tt.w};
        float ov[4];
#pragma unroll
        for (int c = 0; c < 4; c++) {
            int j = jb*4 + c;
            bool colp = (p < MD) && (j == p);
            float tj = colp ? tval : tv[c];
            float mj = (tj >= 0.f) ? 1.f : 0.f;
            float ms  = rowp ? (colp ? npv : hv[c]) : (colp ? hi : sv[c]);
            float ppj = colp ? npv : hv[c];
            ov[c] = mi * mj * (ms - ppi * ppj * ivp);
        }
        float4 o; o.x=ov[0]; o.y=ov[1]; o.z=ov[2]; o.w=ov[3];
        __stcs(&row[jb], o);
    }
}

// -------- tail: mu_n, dict_n, ti_n --------
__global__ void k_tail(const float* __restrict__ mu, const float* __restrict__ dict,
                       const float* __restrict__ x, const float* __restrict__ TI,
                       float* __restrict__ out) {
    int idx = blockIdx.x * 256 + threadIdx.x;   // 65536 threads
    int p = gs_prune;
    float tval = gs_tval;
    // dict_n: one float4 each
    {
        int row = idx >> 4, c4i = idx & 15;
        float4 v;
        if (p < MD && row == p) v = *reinterpret_cast<const float4*>(x + c4i*4);
        else v = *reinterpret_cast<const float4*>(dict + (size_t)row*DD + c4i*4);
        *reinterpret_cast<float4*>(out + OFF_DICT + (size_t)row*DD + c4i*4) = v;
    }
    if (idx < MD) {
        bool rowp = (p < MD) && (idx == p);
        float tn = rowp ? tval : TI[idx];
        out[OFF_TI + idx] = tn;
        float sf = sqrtf(FFC);
        float hi = g_h[idx];
#pragma unroll
        for (int yd = 0; yd < 4; yd++) {
            float val;
            if (tn < 0.f) val = 0.f;
            else if (rowp) val = gs_pm[yd] + gs_c[yd] * gs_npv;
            else val = sf * mu[yd*MD + idx] + gs_c[yd] * hi;
            out[OFF_MU + yd*MD + idx] = val;
        }
    }
}

extern "C" void kernel_launch(void* const* d_in, const int* in_sizes, int n_in,
                              void* d_out, int out_size) {
    const float* dict = (const float*)d_in[0];
    const float* mu   = (const float*)d_in[1];
    const float* sigma= (const float*)d_in[2];
    const float* Q    = (const float*)d_in[3];
    const float* x    = (const float*)d_in[4];
    const float* y    = (const float*)d_in[5];
    const float* nn   = (const float*)d_in[6];
    const float* nd   = (const float*)d_in[7];
    const float* ti   = (const float*)d_in[8];
    const int*   tptr = (const int*)d_in[9];
    float* out = (float*)d_out;

    static int smem_set = 0;
    if (!smem_set) {
        cudaFuncSetAttribute(k_sig, cudaFuncAttributeMaxDynamicSharedMemorySize, SMEM_SIG);
        smem_set = 1;
    }

    k_kdx<<<16, 256>>>(dict, x, ti);
    k_matvec5<<<512, 256>>>(Q, mu);
    k_scalars1<<<1, 256>>>(mu);
    k_sig<<<dim3(32,32), dim3(16,16), SMEM_SIG>>>(dict, sigma, out);
    k_hreduce<<<16, 256>>>();
    k_scalars2<<<1, 256>>>(y, nn, nd, out);
    k_Qh<<<512, 256>>>(Q);
    k_crit<<<16, 256>>>(Q);
    k_finalize<<<1, 32>>>(Q, tptr);
    k_colp<<<16, 256>>>(Q);
    k_Qn<<<4096, 256>>>(Q, out);
    k_sign<<<4096, 256>>>(ti, out);
    k_tail<<<256, 256>>>(mu, dict, x, ti, out);
}